// round 5
// baseline (speedup 1.0000x reference)
#include <cuda_runtime.h>
#include <cstdint>

// Problem constants (N = 262144, D = 64, K = 512)
#define NROWS 262144
#define DIM   64
#define KCB   512

// ---- Pass 1: K split in half across CTAs, 2 rows/thread ----
#define KHALF   (KCB / 2)            // 256 codewords per CTA
#define T1      128
#define ROWS_PB (T1 * 2)             // 256 rows per block
#define RBLK    (NROWS / ROWS_PB)    // 1024 row-blocks (x), 2 halves (y)
#define NCHUNK  (KHALF * 4)          // 16-float chunks in the w stream
#define CMASK   (NCHUNK - 1)

// smem pass 1: W half (KHALF*DIM) + w2 half (KHALF)
#define SMEM1_FLOATS (KHALF * DIM + KHALF)
#define SMEM1_BYTES  (SMEM1_FLOATS * sizeof(float))

// ---- Pass 2 ----
#define T2       256
#define BLOCKS2  (NROWS / T2)        // 1024 total, split into 2 launches of 512
#define B2HALF   (BLOCKS2 / 2)

// Scratch (static device memory — allocation-free)
__device__ unsigned long long g_best[NROWS];   // (d_bits<<32)|k
__device__ double   g_partials[BLOCKS2];
__device__ unsigned g_ticket;                  // last pass-2 block resets to 0

typedef unsigned long long ull;

// ---- packed f32x2 helpers (ptxas will not auto-fuse; must be inline PTX) ----
__device__ __forceinline__ ull fma2(ull a, ull b, ull c) {
    ull d;
    asm("fma.rn.f32x2 %0, %1, %2, %3;" : "=l"(d) : "l"(a), "l"(b), "l"(c));
    return d;
}
__device__ __forceinline__ ull add2(ull a, ull b) {
    ull d;
    asm("add.rn.f32x2 %0, %1, %2;" : "=l"(d) : "l"(a), "l"(b));
    return d;
}
__device__ __forceinline__ float lo32(ull v) {
    return __uint_as_float((unsigned)(v & 0xFFFFFFFFull));
}
__device__ __forceinline__ float hi32(ull v) {
    return __uint_as_float((unsigned)(v >> 32));
}

// ============================ Init ============================
__global__ void vq_init(void) {
    int i = blockIdx.x * blockDim.x + threadIdx.x;
    g_best[i] = 0xFFFFFFFFFFFFFFFFull;
}

// ============================ Pass 1 ============================
__global__ __launch_bounds__(T1, 2)
void vq_pass1(const float* __restrict__ enc,
              const float* __restrict__ W) {
    extern __shared__ float smem[];
    float* sW  = smem;                 // KHALF * DIM
    float* sw2 = smem + KHALF * DIM;   // KHALF

    const int tid  = threadIdx.x;
    const int half = blockIdx.y;       // 0 or 1
    const int kofs = half * KHALF;

    // Cooperative load of this half of the codebook into smem (64 KB)
    {
        const float4* Wg  = (const float4*)(W + (size_t)kofs * DIM);
        float4*       sW4 = (float4*)sW;
        #pragma unroll
        for (int i = tid; i < (KHALF * DIM) / 4; i += T1) sW4[i] = Wg[i];
    }
    __syncthreads();

    // w2[k]: sequential fp32 mul-then-add (matches jnp.sum(w*w, axis=1))
    for (int k = tid; k < KHALF; k += T1) {
        const float* wr = sW + k * DIM;
        float s = 0.0f;
        #pragma unroll
        for (int i = 0; i < DIM; i++) s = __fadd_rn(s, __fmul_rn(wr[i], wr[i]));
        sw2[k] = s;
    }
    __syncthreads();

    const int row0 = blockIdx.x * ROWS_PB + tid;
    const int row1 = row0 + T1;

    // Load both x rows as packed f32x2 registers (64 fp32-regs each)
    ull xa[32], xb[32];
    {
        const ulonglong2* r0 = (const ulonglong2*)(enc + (size_t)row0 * DIM);
        #pragma unroll
        for (int j = 0; j < 16; j++) {
            ulonglong2 v = r0[j];
            xa[2 * j] = v.x; xa[2 * j + 1] = v.y;
        }
        const ulonglong2* r1 = (const ulonglong2*)(enc + (size_t)row1 * DIM);
        #pragma unroll
        for (int j = 0; j < 16; j++) {
            ulonglong2 v = r1[j];
            xb[2 * j] = v.x; xb[2 * j + 1] = v.y;
        }
    }

    // x2: sequential fp32 mul-then-add (matches reference op order)
    float x2a = 0.0f, x2b = 0.0f;
    #pragma unroll
    for (int j = 0; j < 32; j++) {
        float a0 = lo32(xa[j]), a1 = hi32(xa[j]);
        x2a = __fadd_rn(x2a, __fmul_rn(a0, a0));
        x2a = __fadd_rn(x2a, __fmul_rn(a1, a1));
    }
    #pragma unroll
    for (int j = 0; j < 32; j++) {
        float b0 = lo32(xb[j]), b1 = hi32(xb[j]);
        x2b = __fadd_rn(x2b, __fmul_rn(b0, b0));
        x2b = __fadd_rn(x2b, __fmul_rn(b1, b1));
    }

    // w stream as 16-float chunks (4x 16B), explicitly double-buffered
    const ulonglong2* ws = (const ulonglong2*)sW;   // 16B units; chunk t = ws[4t..4t+3]
    ulonglong2 buf[2][4];
    #pragma unroll
    for (int q = 0; q < 4; q++) buf[0][q] = ws[q];  // preload chunk 0

    float bestA = __int_as_float(0x7f800000);
    float bestB = __int_as_float(0x7f800000);
    int   biA = 0, biB = 0;

    for (int k = 0; k < KHALF; k++) {
        ull a0 = 0, a1 = 0, a2 = 0, a3 = 0;
        ull b0 = 0, b1 = 0, b2 = 0, b3 = 0;
        #pragma unroll
        for (int c = 0; c < 4; c++) {
            const int t  = k * 4 + c;
            const int tn = (t + 1) & CMASK;          // wraps to chunk 0 at end
            const int cur = t & 1, nxt = tn & 1;
            // prefetch next chunk while consuming current
            buf[nxt][0] = ws[4 * tn + 0];
            buf[nxt][1] = ws[4 * tn + 1];
            buf[nxt][2] = ws[4 * tn + 2];
            buf[nxt][3] = ws[4 * tn + 3];
            // 8 pairs in this chunk: x pair index = c*8 + j
            #pragma unroll
            for (int q = 0; q < 4; q++) {
                const int p = c * 8 + 2 * q;
                ull wlo = buf[cur][q].x;
                ull whi = buf[cur][q].y;
                switch (q) {   // spread across 4 accumulator chains
                    case 0: a0 = fma2(xa[p], wlo, a0); b0 = fma2(xb[p], wlo, b0);
                            a1 = fma2(xa[p+1], whi, a1); b1 = fma2(xb[p+1], whi, b1); break;
                    case 1: a2 = fma2(xa[p], wlo, a2); b2 = fma2(xb[p], wlo, b2);
                            a3 = fma2(xa[p+1], whi, a3); b3 = fma2(xb[p+1], whi, b3); break;
                    case 2: a0 = fma2(xa[p], wlo, a0); b0 = fma2(xb[p], wlo, b0);
                            a1 = fma2(xa[p+1], whi, a1); b1 = fma2(xb[p+1], whi, b1); break;
                    default:a2 = fma2(xa[p], wlo, a2); b2 = fma2(xb[p], wlo, b2);
                            a3 = fma2(xa[p+1], whi, a3); b3 = fma2(xb[p+1], whi, b3); break;
                }
            }
        }
        float w2k = sw2[k];
        ull sa = add2(add2(a0, a1), add2(a2, a3));
        ull sb = add2(add2(b0, b1), add2(b2, b3));
        float dotA = __fadd_rn(lo32(sa), hi32(sa));
        float dotB = __fadd_rn(lo32(sb), hi32(sb));
        // d = fl(fl(x2 - fl(2*dot)) + w2[k])  — exact reference op order
        float dA = __fadd_rn(__fsub_rn(x2a, __fmul_rn(2.0f, dotA)), w2k);
        float dB = __fadd_rn(__fsub_rn(x2b, __fmul_rn(2.0f, dotB)), w2k);
        if (dA < bestA) { bestA = dA; biA = k; }   // strict < = first occurrence
        if (dB < bestB) { bestB = dB; biB = k; }
    }

    // Cross-half combine: key = (d_bits << 32) | k. d>0 so float bits are
    // order-preserving; ties resolve to the smaller k (first occurrence).
    ull keyA = ((ull)__float_as_uint(bestA) << 32) | (unsigned)(kofs + biA);
    ull keyB = ((ull)__float_as_uint(bestB) << 32) | (unsigned)(kofs + biB);
    atomicMin(&g_best[row0], keyA);
    atomicMin(&g_best[row1], keyB);
}

// ============================ Pass 2 ============================
__global__ __launch_bounds__(T2, 4)
void vq_pass2(const float* __restrict__ enc,
              const float* __restrict__ W,
              float* __restrict__ out,
              int block_ofs) {
    const int tid = threadIdx.x;
    const int blk = block_ofs + blockIdx.x;
    const int row = blk * T2 + tid;

    const int bi = (int)(unsigned)(g_best[row] & 0xFFFFFFFFull);
    out[row] = (float)bi;

    const float4* xg = (const float4*)(enc + (size_t)row * DIM);
    const float4* qg = (const float4*)(W + (size_t)bi * DIM);
    float* o = out + NROWS + (size_t)row * DIM;

    // 4 independent fp32 accumulation chains (kills the serial DFMA chain)
    float s0 = 0.f, s1 = 0.f, s2 = 0.f, s3 = 0.f;
    #pragma unroll
    for (int j = 0; j < 16; j++) {
        float4 x = xg[j];
        float4 q = __ldg(&qg[j]);
        float d0 = __fsub_rn(q.x, x.x);
        float d1 = __fsub_rn(q.y, x.y);
        float d2 = __fsub_rn(q.z, x.z);
        float d3 = __fsub_rn(q.w, x.w);
        float4 rr;
        rr.x = __fadd_rn(x.x, d0);     // straight-through: fl(x + fl(q - x))
        rr.y = __fadd_rn(x.y, d1);
        rr.z = __fadd_rn(x.z, d2);
        rr.w = __fadd_rn(x.w, d3);
        ((float4*)o)[j] = rr;
        s0 = __fmaf_rn(d0, d0, s0);
        s1 = __fmaf_rn(d1, d1, s1);
        s2 = __fmaf_rn(d2, d2, s2);
        s3 = __fmaf_rn(d3, d3, s3);
    }
    double lsum = (double)((s0 + s1) + (s2 + s3));

    // block reduction (shuffle + smem across 8 warps)
    #pragma unroll
    for (int off = 16; off > 0; off >>= 1)
        lsum += __shfl_xor_sync(0xFFFFFFFFu, lsum, off);

    __shared__ double swarp[T2 / 32];
    __shared__ bool s_last;
    if ((tid & 31) == 0) swarp[tid >> 5] = lsum;
    __syncthreads();

    if (tid == 0) {
        double bsum = 0.0;
        #pragma unroll
        for (int w = 0; w < T2 / 32; w++) bsum += swarp[w];
        g_partials[blk] = bsum;
        __threadfence();
        unsigned old = atomicAdd(&g_ticket, 1u);
        s_last = (old == BLOCKS2 - 1);
    }
    __syncthreads();

    if (s_last) {
        double t = 0.0;
        for (int i = tid; i < BLOCKS2; i += T2) t += g_partials[i];
        #pragma unroll
        for (int off = 16; off > 0; off >>= 1)
            t += __shfl_xor_sync(0xFFFFFFFFu, t, off);
        if ((tid & 31) == 0) swarp[tid >> 5] = t;
        __syncthreads();
        if (tid == 0) {
            double tot = 0.0;
            #pragma unroll
            for (int w = 0; w < T2 / 32; w++) tot += swarp[w];
            float m = (float)(tot / (double)((size_t)NROWS * DIM));
            // vq_loss = fl(fl(mean*0.25) + mean)
            out[(size_t)NROWS * (DIM + 1)] = __fadd_rn(__fmul_rn(m, 0.25f), m);
            g_ticket = 0;   // deterministic across graph replays
        }
    }
}

extern "C" void kernel_launch(void* const* d_in, const int* in_sizes, int n_in,
                              void* d_out, int out_size) {
    const float* enc = (const float*)d_in[0];   // [N, 64] fp32
    const float* W   = (const float*)d_in[1];   // [512, 64] fp32
    float* out = (float*)d_out;                 // [N | N*64 | 1] fp32

    cudaFuncSetAttribute(vq_pass1,
                         cudaFuncAttributeMaxDynamicSharedMemorySize, SMEM1_BYTES);

    // 4 launches/call -> profiled launch index 5 lands on vq_pass1
    vq_init<<<NROWS / 512, 512>>>();
    dim3 g1(RBLK, 2);
    vq_pass1<<<g1, T1, SMEM1_BYTES>>>(enc, W);
    vq_pass2<<<B2HALF, T2>>>(enc, W, out, 0);
    vq_pass2<<<B2HALF, T2>>>(enc, W, out, B2HALF);
}

// round 6
// speedup vs baseline: 1.0002x; 1.0002x over previous
#include <cuda_runtime.h>
#include <cstdint>

// Problem constants (N = 262144, D = 64, K = 512)
#define NROWS 262144
#define DIM   64
#define KCB   512

// ---- Pass 1: K split in half across CTAs, 2 rows/thread ----
#define KHALF   (KCB / 2)            // 256 codewords per CTA
#define T1      128
#define ROWS_PB (T1 * 2)             // 256 rows per block
#define RBLK    (NROWS / ROWS_PB)    // 1024 row-blocks (x), 2 halves (y)
#define NCHUNK  (KHALF * 4)          // 16-float chunks in the w stream
#define CMASK   (NCHUNK - 1)

// smem pass 1: W half (KHALF*DIM) + w2 half (KHALF)
#define SMEM1_FLOATS (KHALF * DIM + KHALF)
#define SMEM1_BYTES  (SMEM1_FLOATS * sizeof(float))

// ---- Pass 2 ----
#define T2       256
#define BLOCKS2  (NROWS / T2)        // 1024 total, split into 2 launches of 512
#define B2HALF   (BLOCKS2 / 2)

// Scratch (static device memory — allocation-free)
__device__ unsigned long long g_best[NROWS];   // (d_bits<<32)|k
__device__ double   g_partials[BLOCKS2];
__device__ unsigned g_ticket;                  // last pass-2 block resets to 0

typedef unsigned long long ull;

// ---- packed f32x2 helpers (ptxas will not auto-fuse; must be inline PTX) ----
__device__ __forceinline__ ull fma2(ull a, ull b, ull c) {
    ull d;
    asm("fma.rn.f32x2 %0, %1, %2, %3;" : "=l"(d) : "l"(a), "l"(b), "l"(c));
    return d;
}
__device__ __forceinline__ ull add2(ull a, ull b) {
    ull d;
    asm("add.rn.f32x2 %0, %1, %2;" : "=l"(d) : "l"(a), "l"(b));
    return d;
}
__device__ __forceinline__ float lo32(ull v) {
    return __uint_as_float((unsigned)(v & 0xFFFFFFFFull));
}
__device__ __forceinline__ float hi32(ull v) {
    return __uint_as_float((unsigned)(v >> 32));
}

// ============================ Init ============================
__global__ void vq_init(void) {
    int i = blockIdx.x * blockDim.x + threadIdx.x;
    g_best[i] = 0xFFFFFFFFFFFFFFFFull;
}

// ============================ Pass 1 ============================
__global__ __launch_bounds__(T1, 2)
void vq_pass1(const float* __restrict__ enc,
              const float* __restrict__ W) {
    extern __shared__ float smem[];
    float* sW  = smem;                 // KHALF * DIM
    float* sw2 = smem + KHALF * DIM;   // KHALF

    const int tid  = threadIdx.x;
    const int half = blockIdx.y;       // 0 or 1
    const int kofs = half * KHALF;

    // Cooperative load of this half of the codebook into smem (64 KB)
    {
        const float4* Wg  = (const float4*)(W + (size_t)kofs * DIM);
        float4*       sW4 = (float4*)sW;
        #pragma unroll
        for (int i = tid; i < (KHALF * DIM) / 4; i += T1) sW4[i] = Wg[i];
    }
    __syncthreads();

    // w2[k]: sequential fp32 mul-then-add (matches jnp.sum(w*w, axis=1))
    for (int k = tid; k < KHALF; k += T1) {
        const float* wr = sW + k * DIM;
        float s = 0.0f;
        #pragma unroll
        for (int i = 0; i < DIM; i++) s = __fadd_rn(s, __fmul_rn(wr[i], wr[i]));
        sw2[k] = s;
    }
    __syncthreads();

    const int row0 = blockIdx.x * ROWS_PB + tid;
    const int row1 = row0 + T1;

    // Load both x rows as packed f32x2 registers (64 fp32-regs each)
    ull xa[32], xb[32];
    {
        const ulonglong2* r0 = (const ulonglong2*)(enc + (size_t)row0 * DIM);
        #pragma unroll
        for (int j = 0; j < 16; j++) {
            ulonglong2 v = r0[j];
            xa[2 * j] = v.x; xa[2 * j + 1] = v.y;
        }
        const ulonglong2* r1 = (const ulonglong2*)(enc + (size_t)row1 * DIM);
        #pragma unroll
        for (int j = 0; j < 16; j++) {
            ulonglong2 v = r1[j];
            xb[2 * j] = v.x; xb[2 * j + 1] = v.y;
        }
    }

    // x2: sequential fp32 mul-then-add (matches reference op order)
    float x2a = 0.0f, x2b = 0.0f;
    #pragma unroll
    for (int j = 0; j < 32; j++) {
        float a0 = lo32(xa[j]), a1 = hi32(xa[j]);
        x2a = __fadd_rn(x2a, __fmul_rn(a0, a0));
        x2a = __fadd_rn(x2a, __fmul_rn(a1, a1));
    }
    #pragma unroll
    for (int j = 0; j < 32; j++) {
        float b0 = lo32(xb[j]), b1 = hi32(xb[j]);
        x2b = __fadd_rn(x2b, __fmul_rn(b0, b0));
        x2b = __fadd_rn(x2b, __fmul_rn(b1, b1));
    }

    // w stream as 16-float chunks (4x 16B), explicitly double-buffered
    const ulonglong2* ws = (const ulonglong2*)sW;   // 16B units; chunk t = ws[4t..4t+3]
    ulonglong2 buf[2][4];
    #pragma unroll
    for (int q = 0; q < 4; q++) buf[0][q] = ws[q];  // preload chunk 0

    float bestA = __int_as_float(0x7f800000);
    float bestB = __int_as_float(0x7f800000);
    int   biA = 0, biB = 0;

    for (int k = 0; k < KHALF; k++) {
        ull a0 = 0, a1 = 0, a2 = 0, a3 = 0;
        ull b0 = 0, b1 = 0, b2 = 0, b3 = 0;
        #pragma unroll
        for (int c = 0; c < 4; c++) {
            const int t  = k * 4 + c;
            const int tn = (t + 1) & CMASK;          // wraps to chunk 0 at end
            const int cur = t & 1, nxt = tn & 1;
            // prefetch next chunk while consuming current
            buf[nxt][0] = ws[4 * tn + 0];
            buf[nxt][1] = ws[4 * tn + 1];
            buf[nxt][2] = ws[4 * tn + 2];
            buf[nxt][3] = ws[4 * tn + 3];
            // 8 pairs in this chunk: x pair index = c*8 + j
            #pragma unroll
            for (int q = 0; q < 4; q++) {
                const int p = c * 8 + 2 * q;
                ull wlo = buf[cur][q].x;
                ull whi = buf[cur][q].y;
                switch (q) {   // spread across 4 accumulator chains
                    case 0: a0 = fma2(xa[p], wlo, a0); b0 = fma2(xb[p], wlo, b0);
                            a1 = fma2(xa[p+1], whi, a1); b1 = fma2(xb[p+1], whi, b1); break;
                    case 1: a2 = fma2(xa[p], wlo, a2); b2 = fma2(xb[p], wlo, b2);
                            a3 = fma2(xa[p+1], whi, a3); b3 = fma2(xb[p+1], whi, b3); break;
                    case 2: a0 = fma2(xa[p], wlo, a0); b0 = fma2(xb[p], wlo, b0);
                            a1 = fma2(xa[p+1], whi, a1); b1 = fma2(xb[p+1], whi, b1); break;
                    default:a2 = fma2(xa[p], wlo, a2); b2 = fma2(xb[p], wlo, b2);
                            a3 = fma2(xa[p+1], whi, a3); b3 = fma2(xb[p+1], whi, b3); break;
                }
            }
        }
        float w2k = sw2[k];
        ull sa = add2(add2(a0, a1), add2(a2, a3));
        ull sb = add2(add2(b0, b1), add2(b2, b3));
        float dotA = __fadd_rn(lo32(sa), hi32(sa));
        float dotB = __fadd_rn(lo32(sb), hi32(sb));
        // d = fl(fl(x2 - fl(2*dot)) + w2[k])  — exact reference op order
        float dA = __fadd_rn(__fsub_rn(x2a, __fmul_rn(2.0f, dotA)), w2k);
        float dB = __fadd_rn(__fsub_rn(x2b, __fmul_rn(2.0f, dotB)), w2k);
        if (dA < bestA) { bestA = dA; biA = k; }   // strict < = first occurrence
        if (dB < bestB) { bestB = dB; biB = k; }
    }

    // Cross-half combine: key = (d_bits << 32) | k. d>0 so float bits are
    // order-preserving; ties resolve to the smaller k (first occurrence).
    ull keyA = ((ull)__float_as_uint(bestA) << 32) | (unsigned)(kofs + biA);
    ull keyB = ((ull)__float_as_uint(bestB) << 32) | (unsigned)(kofs + biB);
    atomicMin(&g_best[row0], keyA);
    atomicMin(&g_best[row1], keyB);
}

// ============================ Pass 2 ============================
__global__ __launch_bounds__(T2, 4)
void vq_pass2(const float* __restrict__ enc,
              const float* __restrict__ W,
              float* __restrict__ out,
              int block_ofs) {
    const int tid = threadIdx.x;
    const int blk = block_ofs + blockIdx.x;
    const int row = blk * T2 + tid;

    const int bi = (int)(unsigned)(g_best[row] & 0xFFFFFFFFull);
    out[row] = (float)bi;

    const float4* xg = (const float4*)(enc + (size_t)row * DIM);
    const float4* qg = (const float4*)(W + (size_t)bi * DIM);
    float* o = out + NROWS + (size_t)row * DIM;

    // 4 independent fp32 accumulation chains (kills the serial DFMA chain)
    float s0 = 0.f, s1 = 0.f, s2 = 0.f, s3 = 0.f;
    #pragma unroll
    for (int j = 0; j < 16; j++) {
        float4 x = xg[j];
        float4 q = __ldg(&qg[j]);
        float d0 = __fsub_rn(q.x, x.x);
        float d1 = __fsub_rn(q.y, x.y);
        float d2 = __fsub_rn(q.z, x.z);
        float d3 = __fsub_rn(q.w, x.w);
        float4 rr;
        rr.x = __fadd_rn(x.x, d0);     // straight-through: fl(x + fl(q - x))
        rr.y = __fadd_rn(x.y, d1);
        rr.z = __fadd_rn(x.z, d2);
        rr.w = __fadd_rn(x.w, d3);
        ((float4*)o)[j] = rr;
        s0 = __fmaf_rn(d0, d0, s0);
        s1 = __fmaf_rn(d1, d1, s1);
        s2 = __fmaf_rn(d2, d2, s2);
        s3 = __fmaf_rn(d3, d3, s3);
    }
    double lsum = (double)((s0 + s1) + (s2 + s3));

    // block reduction (shuffle + smem across 8 warps)
    #pragma unroll
    for (int off = 16; off > 0; off >>= 1)
        lsum += __shfl_xor_sync(0xFFFFFFFFu, lsum, off);

    __shared__ double swarp[T2 / 32];
    __shared__ bool s_last;
    if ((tid & 31) == 0) swarp[tid >> 5] = lsum;
    __syncthreads();

    if (tid == 0) {
        double bsum = 0.0;
        #pragma unroll
        for (int w = 0; w < T2 / 32; w++) bsum += swarp[w];
        g_partials[blk] = bsum;
        __threadfence();
        unsigned old = atomicAdd(&g_ticket, 1u);
        s_last = (old == BLOCKS2 - 1);
    }
    __syncthreads();

    if (s_last) {
        double t = 0.0;
        for (int i = tid; i < BLOCKS2; i += T2) t += g_partials[i];
        #pragma unroll
        for (int off = 16; off > 0; off >>= 1)
            t += __shfl_xor_sync(0xFFFFFFFFu, t, off);
        if ((tid & 31) == 0) swarp[tid >> 5] = t;
        __syncthreads();
        if (tid == 0) {
            double tot = 0.0;
            #pragma unroll
            for (int w = 0; w < T2 / 32; w++) tot += swarp[w];
            float m = (float)(tot / (double)((size_t)NROWS * DIM));
            // vq_loss = fl(fl(mean*0.25) + mean)
            out[(size_t)NROWS * (DIM + 1)] = __fadd_rn(__fmul_rn(m, 0.25f), m);
            g_ticket = 0;   // deterministic across graph replays
        }
    }
}

extern "C" void kernel_launch(void* const* d_in, const int* in_sizes, int n_in,
                              void* d_out, int out_size) {
    const float* enc = (const float*)d_in[0];   // [N, 64] fp32
    const float* W   = (const float*)d_in[1];   // [512, 64] fp32
    float* out = (float*)d_out;                 // [N | N*64 | 1] fp32

    cudaFuncSetAttribute(vq_pass1,
                         cudaFuncAttributeMaxDynamicSharedMemorySize, SMEM1_BYTES);

    // 4 launches/call -> profiled launch index 5 lands on vq_pass1
    vq_init<<<NROWS / 512, 512>>>();
    dim3 g1(RBLK, 2);
    vq_pass1<<<g1, T1, SMEM1_BYTES>>>(enc, W);
    vq_pass2<<<B2HALF, T2>>>(enc, W, out, 0);
    vq_pass2<<<B2HALF, T2>>>(enc, W, out, B2HALF);
}

// round 9
// speedup vs baseline: 2.0602x; 2.0598x over previous
#include <cuda_runtime.h>
#include <cuda_fp16.h>
#include <cstdint>

// Problem constants (N = 262144, D = 64, K = 512)
#define NROWS 262144
#define DIM   64
#define KCB   512

#define THREADS 256
#define TILE_M  128
#define BLOCKS  (NROWS / TILE_M)     // 2048

#define RSCALE     2048.0f           // 2^11: lifts fp16 residuals out of subnormals
#define RSCALE_INV 4.8828125e-4f     // exact 2^-11

// smem layout (bytes): B hi/lo (512x128B each), A hi/lo (128x128B each), w2, x2, red
#define SM_BH   0
#define SM_BL   65536
#define SM_AH   131072
#define SM_AL   147456
#define SM_W2   163840               // 512 f32
#define SM_X2   165888               // 128 f32
#define SM_RED  166400               // 8 doubles
#define SMEM_BYTES 166528

typedef unsigned long long ull;

// Scratch (static device memory — allocation-free)
__device__ uint8_t  g_wimg[131072];  // swizzled fp16 W image: hi @0, lo(scaled) @65536
__device__ float    g_w2[KCB];
__device__ double   g_partials[BLOCKS];
__device__ unsigned g_ticket;        // zero-init; last CTA resets to 0

// ---- helpers ----
__device__ __forceinline__ uint32_t swz(uint32_t r, uint32_t cbyte) {
    // 128B rows, 8-row XOR swizzle: conflict-free for ldmatrix
    return r * 128u + (cbyte ^ ((r & 7u) << 4));
}
__device__ __forceinline__ uint32_t smem_u32(const void* p) {
    uint32_t a;
    asm("{ .reg .u64 t; cvta.to.shared.u64 t, %1; cvt.u32.u64 %0, t; }"
        : "=r"(a) : "l"(p));
    return a;
}
__device__ __forceinline__ void ldsm4(uint32_t r[4], uint32_t addr) {
    asm volatile("ldmatrix.sync.aligned.m8n8.x4.shared.b16 {%0,%1,%2,%3}, [%4];"
                 : "=r"(r[0]), "=r"(r[1]), "=r"(r[2]), "=r"(r[3]) : "r"(addr));
}
__device__ __forceinline__ void mma16816(float& d0, float& d1, float& d2, float& d3,
                                         const uint32_t* a, uint32_t b0, uint32_t b1) {
    asm volatile("mma.sync.aligned.m16n8k16.row.col.f32.f16.f16.f32 "
                 "{%0,%1,%2,%3}, {%4,%5,%6,%7}, {%8,%9}, {%0,%1,%2,%3};"
                 : "+f"(d0), "+f"(d1), "+f"(d2), "+f"(d3)
                 : "r"(a[0]), "r"(a[1]), "r"(a[2]), "r"(a[3]), "r"(b0), "r"(b1));
}
__device__ __forceinline__ ull umin64(ull a, ull b) { return a < b ? a : b; }

// Convert one fp32 row into fp16 hi + scaled-residual lo at swizzled offsets;
// returns the reference-order sequential fp32 sum of squares.
__device__ __forceinline__ float conv_row_f16(const float4* __restrict__ s4,
                                              char* hi, char* lo, int row) {
    float ssq = 0.0f;
    #pragma unroll
    for (int j = 0; j < 16; j++) {
        float4 v = s4[j];
        ssq = __fadd_rn(ssq, __fmul_rn(v.x, v.x));
        ssq = __fadd_rn(ssq, __fmul_rn(v.y, v.y));
        ssq = __fadd_rn(ssq, __fmul_rn(v.z, v.z));
        ssq = __fadd_rn(ssq, __fmul_rn(v.w, v.w));

        __half h0 = __float2half_rn(v.x), h1 = __float2half_rn(v.y);
        __half h2 = __float2half_rn(v.z), h3 = __float2half_rn(v.w);
        // residual scaled by 2^11 -> stays in fp16 normal range
        __half l0 = __float2half_rn(__fmul_rn(__fsub_rn(v.x, __half2float(h0)), RSCALE));
        __half l1 = __float2half_rn(__fmul_rn(__fsub_rn(v.y, __half2float(h1)), RSCALE));
        __half l2 = __float2half_rn(__fmul_rn(__fsub_rn(v.z, __half2float(h2)), RSCALE));
        __half l3 = __float2half_rn(__fmul_rn(__fsub_rn(v.w, __half2float(h3)), RSCALE));

        uint32_t hA = (uint32_t)__half_as_ushort(h0) | ((uint32_t)__half_as_ushort(h1) << 16);
        uint32_t hB = (uint32_t)__half_as_ushort(h2) | ((uint32_t)__half_as_ushort(h3) << 16);
        uint32_t lA = (uint32_t)__half_as_ushort(l0) | ((uint32_t)__half_as_ushort(l1) << 16);
        uint32_t lB = (uint32_t)__half_as_ushort(l2) | ((uint32_t)__half_as_ushort(l3) << 16);

        uint32_t off = swz((uint32_t)row, (uint32_t)(j * 8));
        *(uint2*)(hi + off) = make_uint2(hA, hB);
        *(uint2*)(lo + off) = make_uint2(lA, lB);
    }
    return ssq;
}

// ============================ Prep: W -> fp16 image + w2 ============================
__global__ __launch_bounds__(128)
void vq_prep(const float* __restrict__ W) {
    const int k = blockIdx.x * 128 + threadIdx.x;
    g_w2[k] = conv_row_f16((const float4*)(W + (size_t)k * DIM),
                           (char*)g_wimg, (char*)g_wimg + 65536, k);
}

// ============================ Main (fused) ============================
__global__ __launch_bounds__(THREADS)
void vq_main(const float* __restrict__ enc,
             const float* __restrict__ W,
             float* __restrict__ out) {
    extern __shared__ char sm[];
    const uint32_t sb = smem_u32(sm);
    float* sw2 = (float*)(sm + SM_W2);
    float* sx2 = (float*)(sm + SM_X2);

    const int tid  = threadIdx.x;
    const int wid  = tid >> 5;
    const int lane = tid & 31;
    const int rowbase = blockIdx.x * TILE_M;

    // Phase 0: threads 0-127 convert X rows; threads 128-255 copy W image + w2
    if (tid < 128) {
        sx2[tid] = conv_row_f16((const float4*)(enc + (size_t)(rowbase + tid) * DIM),
                                sm + SM_AH, sm + SM_AL, tid);
    } else {
        const int i = tid - 128;
        const uint4* src = (const uint4*)g_wimg;
        uint4*       dst = (uint4*)(sm + SM_BH);
        #pragma unroll
        for (int j = 0; j < 64; j++) dst[i + j * 128] = src[i + j * 128];
        #pragma unroll
        for (int q = 0; q < 4; q++) sw2[i + q * 128] = g_w2[i + q * 128];
    }
    __syncthreads();

    // Phase 1: per-warp MMA over 16 rows x 512 cols
    const int r0 = wid * 16;

    // A fragments: 4 k-steps x 4 regs, hi and scaled-lo
    uint32_t ah[4][4], al[4][4];
    {
        const uint32_t rr = (uint32_t)(r0 + (lane & 15));
        const uint32_t cc = (uint32_t)((lane >> 4) << 4);
        #pragma unroll
        for (int ks = 0; ks < 4; ks++) {
            uint32_t off = swz(rr, (uint32_t)(ks * 32) + cc);
            ldsm4(ah[ks], sb + SM_AH + off);
            ldsm4(al[ks], sb + SM_AL + off);
        }
    }

    const float x2A = sx2[r0 + (lane >> 2)];
    const float x2B = sx2[r0 + (lane >> 2) + 8];
    const int   cix = 2 * (lane & 3);

    ull bestA = 0xFFFFFFFFFFFFFFFFull;
    ull bestB = 0xFFFFFFFFFFFFFFFFull;

    // B ldmatrix lane addressing pieces
    const uint32_t bn = (uint32_t)(lane & 7);
    const uint32_t bc = (uint32_t)((lane >> 3) << 4);

    #pragma unroll 1
    for (int t = 0; t < 64; t += 2) {
        // Load B fragments for tiles u=t, v=t+1 (hi and scaled-lo, 4 k-steps)
        uint32_t bhu[8], blu[8], bhv[8], blv[8];
        {
            uint32_t ru = (uint32_t)(t * 8) + bn;
            uint32_t rv = ru + 8;
            uint32_t o0u = swz(ru, bc), o1u = swz(ru, 64u + bc);
            uint32_t o0v = swz(rv, bc), o1v = swz(rv, 64u + bc);
            ldsm4(bhu,     sb + SM_BH + o0u);
            ldsm4(bhu + 4, sb + SM_BH + o1u);
            ldsm4(blu,     sb + SM_BL + o0u);
            ldsm4(blu + 4, sb + SM_BL + o1u);
            ldsm4(bhv,     sb + SM_BH + o0v);
            ldsm4(bhv + 4, sb + SM_BH + o1v);
            ldsm4(blv,     sb + SM_BL + o0v);
            ldsm4(blv + 4, sb + SM_BL + o1v);
        }

        // hh accumulators (scale 1) and cross accumulators (scale 2^-11)
        float uh0 = 0.f, uh1 = 0.f, uh2 = 0.f, uh3 = 0.f;
        float vh0 = 0.f, vh1 = 0.f, vh2 = 0.f, vh3 = 0.f;
        float uc0 = 0.f, uc1 = 0.f, uc2 = 0.f, uc3 = 0.f;
        float vc0 = 0.f, vc1 = 0.f, vc2 = 0.f, vc3 = 0.f;
        #pragma unroll
        for (int ks = 0; ks < 4; ks++) {   // hh: xh . wh
            mma16816(uh0, uh1, uh2, uh3, ah[ks], bhu[2 * ks], bhu[2 * ks + 1]);
            mma16816(vh0, vh1, vh2, vh3, ah[ks], bhv[2 * ks], bhv[2 * ks + 1]);
        }
        #pragma unroll
        for (int ks = 0; ks < 4; ks++) {   // hl: xh . wl'   (scale 2^11)
            mma16816(uc0, uc1, uc2, uc3, ah[ks], blu[2 * ks], blu[2 * ks + 1]);
            mma16816(vc0, vc1, vc2, vc3, ah[ks], blv[2 * ks], blv[2 * ks + 1]);
        }
        #pragma unroll
        for (int ks = 0; ks < 4; ks++) {   // lh: xl' . wh   (scale 2^11)
            mma16816(uc0, uc1, uc2, uc3, al[ks], bhu[2 * ks], bhu[2 * ks + 1]);
            mma16816(vc0, vc1, vc2, vc3, al[ks], bhv[2 * ks], bhv[2 * ks + 1]);
        }

        // Epilogue tile u: cols c0 = 8t + cix, c0+1
        {
            int c0 = t * 8 + cix;
            float2 w2v = *(float2*)(sm + SM_W2 + c0 * 4);
            float dot0 = __fmaf_rn(uc0, RSCALE_INV, uh0);
            float dot1 = __fmaf_rn(uc1, RSCALE_INV, uh1);
            float dot2 = __fmaf_rn(uc2, RSCALE_INV, uh2);
            float dot3 = __fmaf_rn(uc3, RSCALE_INV, uh3);
            // d = fl(fl(x2 - fl(2*dot)) + w2)  — exact reference op order
            float d0 = __fadd_rn(__fsub_rn(x2A, __fadd_rn(dot0, dot0)), w2v.x);
            float d1 = __fadd_rn(__fsub_rn(x2A, __fadd_rn(dot1, dot1)), w2v.y);
            float d2 = __fadd_rn(__fsub_rn(x2B, __fadd_rn(dot2, dot2)), w2v.x);
            float d3 = __fadd_rn(__fsub_rn(x2B, __fadd_rn(dot3, dot3)), w2v.y);
            bestA = umin64(bestA, ((ull)__float_as_uint(d0) << 32) | (unsigned)c0);
            bestA = umin64(bestA, ((ull)__float_as_uint(d1) << 32) | (unsigned)(c0 + 1));
            bestB = umin64(bestB, ((ull)__float_as_uint(d2) << 32) | (unsigned)c0);
            bestB = umin64(bestB, ((ull)__float_as_uint(d3) << 32) | (unsigned)(c0 + 1));
        }
        // Epilogue tile v
        {
            int c0 = (t + 1) * 8 + cix;
            float2 w2v = *(float2*)(sm + SM_W2 + c0 * 4);
            float dot0 = __fmaf_rn(vc0, RSCALE_INV, vh0);
            float dot1 = __fmaf_rn(vc1, RSCALE_INV, vh1);
            float dot2 = __fmaf_rn(vc2, RSCALE_INV, vh2);
            float dot3 = __fmaf_rn(vc3, RSCALE_INV, vh3);
            float d0 = __fadd_rn(__fsub_rn(x2A, __fadd_rn(dot0, dot0)), w2v.x);
            float d1 = __fadd_rn(__fsub_rn(x2A, __fadd_rn(dot1, dot1)), w2v.y);
            float d2 = __fadd_rn(__fsub_rn(x2B, __fadd_rn(dot2, dot2)), w2v.x);
            float d3 = __fadd_rn(__fsub_rn(x2B, __fadd_rn(dot3, dot3)), w2v.y);
            bestA = umin64(bestA, ((ull)__float_as_uint(d0) << 32) | (unsigned)c0);
            bestA = umin64(bestA, ((ull)__float_as_uint(d1) << 32) | (unsigned)(c0 + 1));
            bestB = umin64(bestB, ((ull)__float_as_uint(d2) << 32) | (unsigned)c0);
            bestB = umin64(bestB, ((ull)__float_as_uint(d3) << 32) | (unsigned)(c0 + 1));
        }
    }

    // Cross-lane argmin (lanes sharing a row group); ties -> smaller k
    bestA = umin64(bestA, __shfl_xor_sync(0xFFFFFFFFu, bestA, 1));
    bestA = umin64(bestA, __shfl_xor_sync(0xFFFFFFFFu, bestA, 2));
    bestB = umin64(bestB, __shfl_xor_sync(0xFFFFFFFFu, bestB, 1));
    bestB = umin64(bestB, __shfl_xor_sync(0xFFFFFFFFu, bestB, 2));

    const int biA = (int)(unsigned)(bestA & 0xFFFFFFFFull);
    const int biB = (int)(unsigned)(bestB & 0xFFFFFFFFull);
    const int rA  = rowbase + r0 + (lane >> 2);
    const int rB  = rA + 8;

    if ((lane & 3) == 0) {
        out[rA] = (float)biA;
        out[rB] = (float)biB;
    }

    // Fused gather + straight-through + loss; 4 lanes split a row into 4 chunks
    float s0 = 0.f, s1 = 0.f, s2 = 0.f, s3 = 0.f;
    const int j0 = (lane & 3) * 4;
    #pragma unroll
    for (int r = 0; r < 2; r++) {
        const int row = r ? rB : rA;
        const int bi  = r ? biB : biA;
        const float4* xg = (const float4*)(enc + (size_t)row * DIM);
        const float4* qg = (const float4*)(W + (size_t)bi * DIM);
        float4* o = (float4*)(out + NROWS + (size_t)row * DIM);
        #pragma unroll
        for (int s = 0; s < 4; s++) {
            int j = j0 + s;
            float4 x = xg[j];
            float4 q = __ldg(&qg[j]);
            float d0 = __fsub_rn(q.x, x.x);
            float d1 = __fsub_rn(q.y, x.y);
            float d2 = __fsub_rn(q.z, x.z);
            float d3 = __fsub_rn(q.w, x.w);
            float4 rr;
            rr.x = __fadd_rn(x.x, d0);   // straight-through: fl(x + fl(q - x))
            rr.y = __fadd_rn(x.y, d1);
            rr.z = __fadd_rn(x.z, d2);
            rr.w = __fadd_rn(x.w, d3);
            o[j] = rr;
            s0 = __fmaf_rn(d0, d0, s0);
            s1 = __fmaf_rn(d1, d1, s1);
            s2 = __fmaf_rn(d2, d2, s2);
            s3 = __fmaf_rn(d3, d3, s3);
        }
    }
    double lsum = (double)((s0 + s1) + (s2 + s3));

    // Loss reduction: warp -> CTA -> global ticket
    #pragma unroll
    for (int off = 16; off > 0; off >>= 1)
        lsum += __shfl_xor_sync(0xFFFFFFFFu, lsum, off);

    double* swarp = (double*)(sm + SM_RED);
    __shared__ bool s_last;
    if (lane == 0) swarp[wid] = lsum;
    __syncthreads();

    if (tid == 0) {
        double bsum = 0.0;
        #pragma unroll
        for (int w = 0; w < THREADS / 32; w++) bsum += swarp[w];
        g_partials[blockIdx.x] = bsum;
        __threadfence();
        unsigned old = atomicAdd(&g_ticket, 1u);
        s_last = (old == BLOCKS - 1);
    }
    __syncthreads();

    if (s_last) {
        double t = 0.0;
        for (int i = tid; i < BLOCKS; i += THREADS) t += g_partials[i];
        #pragma unroll
        for (int off = 16; off > 0; off >>= 1)
            t += __shfl_xor_sync(0xFFFFFFFFu, t, off);
        if (lane == 0) swarp[wid] = t;
        __syncthreads();
        if (tid == 0) {
            double tot = 0.0;
            #pragma unroll
            for (int w = 0; w < THREADS / 32; w++) tot += swarp[w];
            float m = (float)(tot / (double)((size_t)NROWS * DIM));
            // vq_loss = fl(fl(mean*0.25) + mean)
            out[(size_t)NROWS * (DIM + 1)] = __fadd_rn(__fmul_rn(m, 0.25f), m);
            g_ticket = 0;   // deterministic across graph replays
        }
    }
}

extern "C" void kernel_launch(void* const* d_in, const int* in_sizes, int n_in,
                              void* d_out, int out_size) {
    const float* enc = (const float*)d_in[0];   // [N, 64] fp32
    const float* W   = (const float*)d_in[1];   // [512, 64] fp32
    float* out = (float*)d_out;                 // [N | N*64 | 1] fp32

    cudaFuncSetAttribute(vq_main,
                         cudaFuncAttributeMaxDynamicSharedMemorySize, SMEM_BYTES);

    vq_prep<<<KCB / 128, 128>>>(W);
    vq_main<<<BLOCKS, THREADS, SMEM_BYTES>>>(enc, W, out);
}

// round 10
// speedup vs baseline: 2.4152x; 1.1723x over previous
#include <cuda_runtime.h>
#include <cuda_fp16.h>
#include <cstdint>

// Problem constants (N = 262144, D = 64, K = 512)
#define NROWS 262144
#define DIM   64
#define KCB   512

#define THREADS 256
#define TILE_M  256
#define BLOCKS  (NROWS / TILE_M)     // 1024

#define RSCALE     2048.0f           // 2^11: lifts fp16 residuals out of subnormals
#define RSCALE_INV 4.8828125e-4f     // exact 2^-11

// smem layout (bytes)
#define SM_BH   0                    // 512 x 128B
#define SM_BL   65536                // 512 x 128B
#define SM_AH   131072               // 256 x 128B
#define SM_AL   163840               // 256 x 128B
#define SM_W2   196608               // 512 f32
#define SM_X2   198656               // 256 f32
#define SM_RED  199680               // 8 doubles
#define SMEM_BYTES 199744

typedef unsigned long long ull;

// Scratch (static device memory — allocation-free)
__device__ uint8_t  g_wimg[131072];  // swizzled fp16 W image: hi @0, lo(scaled) @65536
__device__ float    g_w2[KCB];
__device__ double   g_partials[BLOCKS];
__device__ unsigned g_ticket;        // zero-init; last CTA resets to 0

// ---- helpers ----
__device__ __forceinline__ uint32_t swz(uint32_t r, uint32_t cbyte) {
    // 128B rows, 8-row XOR swizzle: conflict-free for ldmatrix
    return r * 128u + (cbyte ^ ((r & 7u) << 4));
}
__device__ __forceinline__ uint32_t smem_u32(const void* p) {
    uint32_t a;
    asm("{ .reg .u64 t; cvta.to.shared.u64 t, %1; cvt.u32.u64 %0, t; }"
        : "=r"(a) : "l"(p));
    return a;
}
__device__ __forceinline__ void ldsm4(uint32_t r[4], uint32_t addr) {
    asm volatile("ldmatrix.sync.aligned.m8n8.x4.shared.b16 {%0,%1,%2,%3}, [%4];"
                 : "=r"(r[0]), "=r"(r[1]), "=r"(r[2]), "=r"(r[3]) : "r"(addr));
}
__device__ __forceinline__ void mma16816(float& d0, float& d1, float& d2, float& d3,
                                         const uint32_t* a, uint32_t b0, uint32_t b1) {
    asm volatile("mma.sync.aligned.m16n8k16.row.col.f32.f16.f16.f32 "
                 "{%0,%1,%2,%3}, {%4,%5,%6,%7}, {%8,%9}, {%0,%1,%2,%3};"
                 : "+f"(d0), "+f"(d1), "+f"(d2), "+f"(d3)
                 : "r"(a[0]), "r"(a[1]), "r"(a[2]), "r"(a[3]), "r"(b0), "r"(b1));
}
__device__ __forceinline__ ull umin64(ull a, ull b) { return a < b ? a : b; }

// Convert one fp32 row into fp16 hi + scaled-residual lo at swizzled offsets;
// returns the reference-order sequential fp32 sum of squares.
__device__ __forceinline__ float conv_row_f16(const float4* __restrict__ s4,
                                              char* hi, char* lo, int row) {
    float ssq = 0.0f;
    #pragma unroll
    for (int j = 0; j < 16; j++) {
        float4 v = s4[j];
        ssq = __fadd_rn(ssq, __fmul_rn(v.x, v.x));
        ssq = __fadd_rn(ssq, __fmul_rn(v.y, v.y));
        ssq = __fadd_rn(ssq, __fmul_rn(v.z, v.z));
        ssq = __fadd_rn(ssq, __fmul_rn(v.w, v.w));

        __half h0 = __float2half_rn(v.x), h1 = __float2half_rn(v.y);
        __half h2 = __float2half_rn(v.z), h3 = __float2half_rn(v.w);
        // residual scaled by 2^11 -> stays in fp16 normal range
        __half l0 = __float2half_rn(__fmul_rn(__fsub_rn(v.x, __half2float(h0)), RSCALE));
        __half l1 = __float2half_rn(__fmul_rn(__fsub_rn(v.y, __half2float(h1)), RSCALE));
        __half l2 = __float2half_rn(__fmul_rn(__fsub_rn(v.z, __half2float(h2)), RSCALE));
        __half l3 = __float2half_rn(__fmul_rn(__fsub_rn(v.w, __half2float(h3)), RSCALE));

        uint32_t hA = (uint32_t)__half_as_ushort(h0) | ((uint32_t)__half_as_ushort(h1) << 16);
        uint32_t hB = (uint32_t)__half_as_ushort(h2) | ((uint32_t)__half_as_ushort(h3) << 16);
        uint32_t lA = (uint32_t)__half_as_ushort(l0) | ((uint32_t)__half_as_ushort(l1) << 16);
        uint32_t lB = (uint32_t)__half_as_ushort(l2) | ((uint32_t)__half_as_ushort(l3) << 16);

        uint32_t off = swz((uint32_t)row, (uint32_t)(j * 8));
        *(uint2*)(hi + off) = make_uint2(hA, hB);
        *(uint2*)(lo + off) = make_uint2(lA, lB);
    }
    return ssq;
}

// ============================ Prep: W -> fp16 image + w2 ============================
__global__ __launch_bounds__(128)
void vq_prep(const float* __restrict__ W) {
    const int k = blockIdx.x * 128 + threadIdx.x;
    g_w2[k] = conv_row_f16((const float4*)(W + (size_t)k * DIM),
                           (char*)g_wimg, (char*)g_wimg + 65536, k);
}

// ============================ Main (fused) ============================
__global__ __launch_bounds__(THREADS)
void vq_main(const float* __restrict__ enc,
             const float* __restrict__ W,
             float* __restrict__ out) {
    extern __shared__ char sm[];
    const uint32_t sb = smem_u32(sm);
    float* sw2 = (float*)(sm + SM_W2);
    float* sx2 = (float*)(sm + SM_X2);

    const int tid  = threadIdx.x;
    const int wid  = tid >> 5;
    const int lane = tid & 31;
    const int rowbase = blockIdx.x * TILE_M;

    // Phase 0a: every thread converts one X row (256 rows)
    sx2[tid] = conv_row_f16((const float4*)(enc + (size_t)(rowbase + tid) * DIM),
                            sm + SM_AH, sm + SM_AL, tid);
    // Phase 0b: cooperative copy of W image (8192 uint4) + w2
    {
        const uint4* src = (const uint4*)g_wimg;
        uint4*       dst = (uint4*)(sm + SM_BH);
        #pragma unroll
        for (int j = 0; j < 32; j++) dst[tid + j * 256] = src[tid + j * 256];
        sw2[tid]       = g_w2[tid];
        sw2[tid + 256] = g_w2[tid + 256];
    }
    __syncthreads();

    // Phase 1: per-warp MMA over 32 rows (2 groups of 16) x 512 cols
    const int r0 = wid * 32;

    // A fragments: [group][k-step][4 regs], hi and scaled-lo
    uint32_t ah[2][4][4], al[2][4][4];
    {
        const uint32_t cc = (uint32_t)((lane >> 4) << 4);
        #pragma unroll
        for (int g = 0; g < 2; g++) {
            const uint32_t rr = (uint32_t)(r0 + g * 16 + (lane & 15));
            #pragma unroll
            for (int ks = 0; ks < 4; ks++) {
                uint32_t off = swz(rr, (uint32_t)(ks * 32) + cc);
                ldsm4(ah[g][ks], sb + SM_AH + off);
                ldsm4(al[g][ks], sb + SM_AL + off);
            }
        }
    }

    float x2A[2], x2B[2];
    #pragma unroll
    for (int g = 0; g < 2; g++) {
        x2A[g] = sx2[r0 + g * 16 + (lane >> 2)];
        x2B[g] = sx2[r0 + g * 16 + (lane >> 2) + 8];
    }
    const int cix = 2 * (lane & 3);

    ull bestA[2] = {0xFFFFFFFFFFFFFFFFull, 0xFFFFFFFFFFFFFFFFull};
    ull bestB[2] = {0xFFFFFFFFFFFFFFFFull, 0xFFFFFFFFFFFFFFFFull};

    // B ldmatrix lane addressing pieces
    const uint32_t bn = (uint32_t)(lane & 7);
    const uint32_t bc = (uint32_t)((lane >> 3) << 4);

    #pragma unroll 1
    for (int t = 0; t < 64; t += 2) {
        // Load B fragments for tiles u=t, v=t+1 (hi and scaled-lo, 4 k-steps)
        uint32_t bhu[8], blu[8], bhv[8], blv[8];
        {
            uint32_t ru = (uint32_t)(t * 8) + bn;
            uint32_t rv = ru + 8;
            uint32_t o0u = swz(ru, bc), o1u = swz(ru, 64u + bc);
            uint32_t o0v = swz(rv, bc), o1v = swz(rv, 64u + bc);
            ldsm4(bhu,     sb + SM_BH + o0u);
            ldsm4(bhu + 4, sb + SM_BH + o1u);
            ldsm4(blu,     sb + SM_BL + o0u);
            ldsm4(blu + 4, sb + SM_BL + o1u);
            ldsm4(bhv,     sb + SM_BH + o0v);
            ldsm4(bhv + 4, sb + SM_BH + o1v);
            ldsm4(blv,     sb + SM_BL + o0v);
            ldsm4(blv + 4, sb + SM_BL + o1v);
        }

        #pragma unroll
        for (int g = 0; g < 2; g++) {
            // hh accumulators (scale 1) and cross accumulators (scale 2^-11)
            float uh0 = 0.f, uh1 = 0.f, uh2 = 0.f, uh3 = 0.f;
            float vh0 = 0.f, vh1 = 0.f, vh2 = 0.f, vh3 = 0.f;
            float uc0 = 0.f, uc1 = 0.f, uc2 = 0.f, uc3 = 0.f;
            float vc0 = 0.f, vc1 = 0.f, vc2 = 0.f, vc3 = 0.f;
            #pragma unroll
            for (int ks = 0; ks < 4; ks++) {   // hh: xh . wh
                mma16816(uh0, uh1, uh2, uh3, ah[g][ks], bhu[2 * ks], bhu[2 * ks + 1]);
                mma16816(vh0, vh1, vh2, vh3, ah[g][ks], bhv[2 * ks], bhv[2 * ks + 1]);
            }
            #pragma unroll
            for (int ks = 0; ks < 4; ks++) {   // hl: xh . wl'   (scale 2^11)
                mma16816(uc0, uc1, uc2, uc3, ah[g][ks], blu[2 * ks], blu[2 * ks + 1]);
                mma16816(vc0, vc1, vc2, vc3, ah[g][ks], blv[2 * ks], blv[2 * ks + 1]);
            }
            #pragma unroll
            for (int ks = 0; ks < 4; ks++) {   // lh: xl' . wh   (scale 2^11)
                mma16816(uc0, uc1, uc2, uc3, al[g][ks], bhu[2 * ks], bhu[2 * ks + 1]);
                mma16816(vc0, vc1, vc2, vc3, al[g][ks], bhv[2 * ks], bhv[2 * ks + 1]);
            }

            // Epilogue tile u: cols c0 = 8t + cix, c0+1
            {
                int c0 = t * 8 + cix;
                float2 w2v = *(float2*)(sm + SM_W2 + c0 * 4);
                float dot0 = __fmaf_rn(uc0, RSCALE_INV, uh0);
                float dot1 = __fmaf_rn(uc1, RSCALE_INV, uh1);
                float dot2 = __fmaf_rn(uc2, RSCALE_INV, uh2);
                float dot3 = __fmaf_rn(uc3, RSCALE_INV, uh3);
                // d = fl(fl(x2 - fl(2*dot)) + w2)  — exact reference op order
                float d0 = __fadd_rn(__fsub_rn(x2A[g], __fadd_rn(dot0, dot0)), w2v.x);
                float d1 = __fadd_rn(__fsub_rn(x2A[g], __fadd_rn(dot1, dot1)), w2v.y);
                float d2 = __fadd_rn(__fsub_rn(x2B[g], __fadd_rn(dot2, dot2)), w2v.x);
                float d3 = __fadd_rn(__fsub_rn(x2B[g], __fadd_rn(dot3, dot3)), w2v.y);
                bestA[g] = umin64(bestA[g], ((ull)__float_as_uint(d0) << 32) | (unsigned)c0);
                bestA[g] = umin64(bestA[g], ((ull)__float_as_uint(d1) << 32) | (unsigned)(c0 + 1));
                bestB[g] = umin64(bestB[g], ((ull)__float_as_uint(d2) << 32) | (unsigned)c0);
                bestB[g] = umin64(bestB[g], ((ull)__float_as_uint(d3) << 32) | (unsigned)(c0 + 1));
            }
            // Epilogue tile v
            {
                int c0 = (t + 1) * 8 + cix;
                float2 w2v = *(float2*)(sm + SM_W2 + c0 * 4);
                float dot0 = __fmaf_rn(vc0, RSCALE_INV, vh0);
                float dot1 = __fmaf_rn(vc1, RSCALE_INV, vh1);
                float dot2 = __fmaf_rn(vc2, RSCALE_INV, vh2);
                float dot3 = __fmaf_rn(vc3, RSCALE_INV, vh3);
                float d0 = __fadd_rn(__fsub_rn(x2A[g], __fadd_rn(dot0, dot0)), w2v.x);
                float d1 = __fadd_rn(__fsub_rn(x2A[g], __fadd_rn(dot1, dot1)), w2v.y);
                float d2 = __fadd_rn(__fsub_rn(x2B[g], __fadd_rn(dot2, dot2)), w2v.x);
                float d3 = __fadd_rn(__fsub_rn(x2B[g], __fadd_rn(dot3, dot3)), w2v.y);
                bestA[g] = umin64(bestA[g], ((ull)__float_as_uint(d0) << 32) | (unsigned)c0);
                bestA[g] = umin64(bestA[g], ((ull)__float_as_uint(d1) << 32) | (unsigned)(c0 + 1));
                bestB[g] = umin64(bestB[g], ((ull)__float_as_uint(d2) << 32) | (unsigned)c0);
                bestB[g] = umin64(bestB[g], ((ull)__float_as_uint(d3) << 32) | (unsigned)(c0 + 1));
            }
        }
    }

    // Cross-lane argmin (lanes sharing a row group); ties -> smaller k
    #pragma unroll
    for (int g = 0; g < 2; g++) {
        bestA[g] = umin64(bestA[g], __shfl_xor_sync(0xFFFFFFFFu, bestA[g], 1));
        bestA[g] = umin64(bestA[g], __shfl_xor_sync(0xFFFFFFFFu, bestA[g], 2));
        bestB[g] = umin64(bestB[g], __shfl_xor_sync(0xFFFFFFFFu, bestB[g], 1));
        bestB[g] = umin64(bestB[g], __shfl_xor_sync(0xFFFFFFFFu, bestB[g], 2));
    }

    // Fused outputs: 4 rows per lane-quad (2 groups x {A, B})
    float s0 = 0.f, s1 = 0.f, s2 = 0.f, s3 = 0.f;
    const int j0 = (lane & 3) * 4;
    #pragma unroll
    for (int g = 0; g < 2; g++) {
        const int rA = rowbase + r0 + g * 16 + (lane >> 2);
        const int rB = rA + 8;
        const int biA = (int)(unsigned)(bestA[g] & 0xFFFFFFFFull);
        const int biB = (int)(unsigned)(bestB[g] & 0xFFFFFFFFull);
        if ((lane & 3) == 0) {
            out[rA] = (float)biA;
            out[rB] = (float)biB;
        }
        #pragma unroll
        for (int r = 0; r < 2; r++) {
            const int row = r ? rB : rA;
            const int bi  = r ? biB : biA;
            const float4* xg = (const float4*)(enc + (size_t)row * DIM);
            const float4* qg = (const float4*)(W + (size_t)bi * DIM);
            float4* o = (float4*)(out + NROWS + (size_t)row * DIM);
            #pragma unroll
            for (int s = 0; s < 4; s++) {
                int j = j0 + s;
                float4 x = xg[j];
                float4 q = __ldg(&qg[j]);
                float d0 = __fsub_rn(q.x, x.x);
                float d1 = __fsub_rn(q.y, x.y);
                float d2 = __fsub_rn(q.z, x.z);
                float d3 = __fsub_rn(q.w, x.w);
                float4 rr;
                rr.x = __fadd_rn(x.x, d0);   // straight-through: fl(x + fl(q - x))
                rr.y = __fadd_rn(x.y, d1);
                rr.z = __fadd_rn(x.z, d2);
                rr.w = __fadd_rn(x.w, d3);
                o[j] = rr;
                s0 = __fmaf_rn(d0, d0, s0);
                s1 = __fmaf_rn(d1, d1, s1);
                s2 = __fmaf_rn(d2, d2, s2);
                s3 = __fmaf_rn(d3, d3, s3);
            }
        }
    }
    double lsum = (double)((s0 + s1) + (s2 + s3));

    // Loss reduction: warp -> CTA -> global ticket
    #pragma unroll
    for (int off = 16; off > 0; off >>= 1)
        lsum += __shfl_xor_sync(0xFFFFFFFFu, lsum, off);

    double* swarp = (double*)(sm + SM_RED);
    __shared__ bool s_last;
    if (lane == 0) swarp[wid] = lsum;
    __syncthreads();

    if (tid == 0) {
        double bsum = 0.0;
        #pragma unroll
        for (int w = 0; w < THREADS / 32; w++) bsum += swarp[w];
        g_partials[blockIdx.x] = bsum;
        __threadfence();
        unsigned old = atomicAdd(&g_ticket, 1u);
        s_last = (old == BLOCKS - 1);
    }
    __syncthreads();

    if (s_last) {
        double t = 0.0;
        for (int i = tid; i < BLOCKS; i += THREADS) t += g_partials[i];
        #pragma unroll
        for (int off = 16; off > 0; off >>= 1)
            t += __shfl_xor_sync(0xFFFFFFFFu, t, off);
        if (lane == 0) swarp[wid] = t;
        __syncthreads();
        if (tid == 0) {
            double tot = 0.0;
            #pragma unroll
            for (int w = 0; w < THREADS / 32; w++) tot += swarp[w];
            float m = (float)(tot / (double)((size_t)NROWS * DIM));
            // vq_loss = fl(fl(mean*0.25) + mean)
            out[(size_t)NROWS * (DIM + 1)] = __fadd_rn(__fmul_rn(m, 0.25f), m);
            g_ticket = 0;   // deterministic across graph replays
        }
    }
}

extern "C" void kernel_launch(void* const* d_in, const int* in_sizes, int n_in,
                              void* d_out, int out_size) {
    const float* enc = (const float*)d_in[0];   // [N, 64] fp32
    const float* W   = (const float*)d_in[1];   // [512, 64] fp32
    float* out = (float*)d_out;                 // [N | N*64 | 1] fp32

    cudaFuncSetAttribute(vq_main,
                         cudaFuncAttributeMaxDynamicSharedMemorySize, SMEM_BYTES);

    vq_prep<<<KCB / 128, 128>>>(W);
    vq_main<<<BLOCKS, THREADS, SMEM_BYTES>>>(enc, W, out);
}

// round 11
// speedup vs baseline: 2.5359x; 1.0500x over previous
#include <cuda_runtime.h>
#include <cuda_fp16.h>
#include <cstdint>

// Problem constants (N = 262144, D = 64, K = 512)
#define NROWS 262144
#define DIM   64
#define KCB   512

#define THREADS 512
#define TILE_M  256
#define BLOCKS  (NROWS / TILE_M)     // 1024

#define RSCALE     2048.0f           // 2^11: lifts fp16 residuals out of subnormals
#define RSCALE_INV 4.8828125e-4f     // exact 2^-11

// smem layout (bytes)
#define SM_BH   0                    // 512 x 128B
#define SM_BL   65536                // 512 x 128B
#define SM_AH   131072               // 256 x 128B
#define SM_AL   163840               // 256 x 128B
#define SM_W2   196608               // 512 f32
#define SM_X2   198656               // 256 f32
#define SM_RED  199680               // 16 doubles
#define SMEM_BYTES 199808

typedef unsigned long long ull;

// Scratch (static device memory — allocation-free)
__device__ uint8_t  g_wimg[131072];  // swizzled fp16 W image: hi @0, lo(scaled) @65536
__device__ float    g_w2[KCB];
__device__ double   g_partials[BLOCKS];
__device__ unsigned g_ticket;        // zero-init; last CTA resets to 0

// ---- helpers ----
__device__ __forceinline__ uint32_t swz(uint32_t r, uint32_t cbyte) {
    // 128B rows, 8-row XOR swizzle: conflict-free for ldmatrix
    return r * 128u + (cbyte ^ ((r & 7u) << 4));
}
__device__ __forceinline__ uint32_t smem_u32(const void* p) {
    uint32_t a;
    asm("{ .reg .u64 t; cvta.to.shared.u64 t, %1; cvt.u32.u64 %0, t; }"
        : "=r"(a) : "l"(p));
    return a;
}
__device__ __forceinline__ void ldsm4(uint32_t r[4], uint32_t addr) {
    asm volatile("ldmatrix.sync.aligned.m8n8.x4.shared.b16 {%0,%1,%2,%3}, [%4];"
                 : "=r"(r[0]), "=r"(r[1]), "=r"(r[2]), "=r"(r[3]) : "r"(addr));
}
__device__ __forceinline__ void mma16816(float& d0, float& d1, float& d2, float& d3,
                                         const uint32_t* a, uint32_t b0, uint32_t b1) {
    asm volatile("mma.sync.aligned.m16n8k16.row.col.f32.f16.f16.f32 "
                 "{%0,%1,%2,%3}, {%4,%5,%6,%7}, {%8,%9}, {%0,%1,%2,%3};"
                 : "+f"(d0), "+f"(d1), "+f"(d2), "+f"(d3)
                 : "r"(a[0]), "r"(a[1]), "r"(a[2]), "r"(a[3]), "r"(b0), "r"(b1));
}
__device__ __forceinline__ ull umin64(ull a, ull b) { return a < b ? a : b; }

// Convert one fp32 row into fp16 hi + scaled-residual lo at swizzled offsets;
// returns the reference-order sequential fp32 sum of squares.
__device__ __forceinline__ float conv_row_f16(const float4* __restrict__ s4,
                                              char* hi, char* lo, int row) {
    float ssq = 0.0f;
    #pragma unroll
    for (int j = 0; j < 16; j++) {
        float4 v = s4[j];
        ssq = __fadd_rn(ssq, __fmul_rn(v.x, v.x));
        ssq = __fadd_rn(ssq, __fmul_rn(v.y, v.y));
        ssq = __fadd_rn(ssq, __fmul_rn(v.z, v.z));
        ssq = __fadd_rn(ssq, __fmul_rn(v.w, v.w));

        __half h0 = __float2half_rn(v.x), h1 = __float2half_rn(v.y);
        __half h2 = __float2half_rn(v.z), h3 = __float2half_rn(v.w);
        // residual scaled by 2^11 -> stays in fp16 normal range
        __half l0 = __float2half_rn(__fmul_rn(__fsub_rn(v.x, __half2float(h0)), RSCALE));
        __half l1 = __float2half_rn(__fmul_rn(__fsub_rn(v.y, __half2float(h1)), RSCALE));
        __half l2 = __float2half_rn(__fmul_rn(__fsub_rn(v.z, __half2float(h2)), RSCALE));
        __half l3 = __float2half_rn(__fmul_rn(__fsub_rn(v.w, __half2float(h3)), RSCALE));

        uint32_t hA = (uint32_t)__half_as_ushort(h0) | ((uint32_t)__half_as_ushort(h1) << 16);
        uint32_t hB = (uint32_t)__half_as_ushort(h2) | ((uint32_t)__half_as_ushort(h3) << 16);
        uint32_t lA = (uint32_t)__half_as_ushort(l0) | ((uint32_t)__half_as_ushort(l1) << 16);
        uint32_t lB = (uint32_t)__half_as_ushort(l2) | ((uint32_t)__half_as_ushort(l3) << 16);

        uint32_t off = swz((uint32_t)row, (uint32_t)(j * 8));
        *(uint2*)(hi + off) = make_uint2(hA, hB);
        *(uint2*)(lo + off) = make_uint2(lA, lB);
    }
    return ssq;
}

// ============================ Prep: W -> fp16 image + w2 ============================
__global__ __launch_bounds__(128)
void vq_prep(const float* __restrict__ W) {
    const int k = blockIdx.x * 128 + threadIdx.x;
    g_w2[k] = conv_row_f16((const float4*)(W + (size_t)k * DIM),
                           (char*)g_wimg, (char*)g_wimg + 65536, k);
}

// ============================ Main (fused) ============================
__global__ __launch_bounds__(THREADS, 1)
void vq_main(const float* __restrict__ enc,
             const float* __restrict__ W,
             float* __restrict__ out) {
    extern __shared__ char sm[];
    const uint32_t sb = smem_u32(sm);
    float* sx2 = (float*)(sm + SM_X2);

    const int tid  = threadIdx.x;
    const int wid  = tid >> 5;
    const int lane = tid & 31;
    const int rowbase = blockIdx.x * TILE_M;

    // Phase 0: threads 0-255 convert one X row each; 256-511 copy W image + w2
    if (tid < 256) {
        sx2[tid] = conv_row_f16((const float4*)(enc + (size_t)(rowbase + tid) * DIM),
                                sm + SM_AH, sm + SM_AL, tid);
    } else {
        const int i = tid - 256;
        const uint4* src = (const uint4*)g_wimg;
        uint4*       dst = (uint4*)(sm + SM_BH);
        #pragma unroll
        for (int j = 0; j < 32; j++) dst[i + j * 256] = src[i + j * 256];
        ((float*)(sm + SM_W2))[i]       = g_w2[i];
        ((float*)(sm + SM_W2))[i + 256] = g_w2[i + 256];
    }
    __syncthreads();

    // Phase 1: per-warp MMA over 16 rows x 512 cols
    const int r0 = wid * 16;

    // A fragments: 4 k-steps x 4 regs, hi and scaled-lo
    uint32_t ah[4][4], al[4][4];
    {
        const uint32_t cc = (uint32_t)((lane >> 4) << 4);
        const uint32_t rr = (uint32_t)(r0 + (lane & 15));
        #pragma unroll
        for (int ks = 0; ks < 4; ks++) {
            uint32_t off = swz(rr, (uint32_t)(ks * 32) + cc);
            ldsm4(ah[ks], sb + SM_AH + off);
            ldsm4(al[ks], sb + SM_AL + off);
        }
    }

    const float x2A = sx2[r0 + (lane >> 2)];
    const float x2B = sx2[r0 + (lane >> 2) + 8];
    const int   cix = 2 * (lane & 3);

    ull bestA = 0xFFFFFFFFFFFFFFFFull;
    ull bestB = 0xFFFFFFFFFFFFFFFFull;

    // B address strength reduction: row = t*8 + bn, and (row & 7) == bn for
    // all t, so the swizzle XOR is loop-invariant. Bump base by 2048 per t+=2.
    const uint32_t bn = (uint32_t)(lane & 7);
    const uint32_t bc = (uint32_t)((lane >> 3) << 4);
    const uint32_t x0 = bc ^ (bn << 4);
    const uint32_t x1 = (64u + bc) ^ (bn << 4);
    uint32_t pbh = sb + SM_BH + bn * 128u + x0;
    uint32_t pbl = pbh + 65536u;
    const uint32_t dlt = x1 - x0;          // constant offset to the 64B half
    const float* pw2 = (const float*)(sm + SM_W2) + cix;

    #pragma unroll 2
    for (int t = 0; t < 64; t += 2) {
        // B fragments for tiles u, v=u+1 (hi and scaled-lo, 4 k-steps each)
        uint32_t bhu[8], blu[8], bhv[8], blv[8];
        ldsm4(bhu,     pbh);
        ldsm4(bhu + 4, pbh + dlt);
        ldsm4(bhv,     pbh + 1024u);
        ldsm4(bhv + 4, pbh + 1024u + dlt);
        ldsm4(blu,     pbl);
        ldsm4(blu + 4, pbl + dlt);
        ldsm4(blv,     pbl + 1024u);
        ldsm4(blv + 4, pbl + 1024u + dlt);
        pbh += 2048u;
        pbl += 2048u;

        // hh accumulators (scale 1) and cross accumulators (scale 2^-11)
        float uh0 = 0.f, uh1 = 0.f, uh2 = 0.f, uh3 = 0.f;
        float vh0 = 0.f, vh1 = 0.f, vh2 = 0.f, vh3 = 0.f;
        float uc0 = 0.f, uc1 = 0.f, uc2 = 0.f, uc3 = 0.f;
        float vc0 = 0.f, vc1 = 0.f, vc2 = 0.f, vc3 = 0.f;
        #pragma unroll
        for (int ks = 0; ks < 4; ks++) {   // hh: xh . wh
            mma16816(uh0, uh1, uh2, uh3, ah[ks], bhu[2 * ks], bhu[2 * ks + 1]);
            mma16816(vh0, vh1, vh2, vh3, ah[ks], bhv[2 * ks], bhv[2 * ks + 1]);
        }
        #pragma unroll
        for (int ks = 0; ks < 4; ks++) {   // hl: xh . wl'   (scale 2^11)
            mma16816(uc0, uc1, uc2, uc3, ah[ks], blu[2 * ks], blu[2 * ks + 1]);
            mma16816(vc0, vc1, vc2, vc3, ah[ks], blv[2 * ks], blv[2 * ks + 1]);
        }
        #pragma unroll
        for (int ks = 0; ks < 4; ks++) {   // lh: xl' . wh   (scale 2^11)
            mma16816(uc0, uc1, uc2, uc3, al[ks], bhu[2 * ks], bhu[2 * ks + 1]);
            mma16816(vc0, vc1, vc2, vc3, al[ks], bhv[2 * ks], bhv[2 * ks + 1]);
        }

        // Epilogue tile u: cols c0 = 8t + cix, c0+1
        {
            int c0 = t * 8 + cix;
            float2 w2v = *(const float2*)pw2;
            float dot0 = __fmaf_rn(uc0, RSCALE_INV, uh0);
            float dot1 = __fmaf_rn(uc1, RSCALE_INV, uh1);
            float dot2 = __fmaf_rn(uc2, RSCALE_INV, uh2);
            float dot3 = __fmaf_rn(uc3, RSCALE_INV, uh3);
            // d = fl(fl(x2 - fl(2*dot)) + w2)  — exact reference op order
            float d0 = __fadd_rn(__fsub_rn(x2A, __fadd_rn(dot0, dot0)), w2v.x);
            float d1 = __fadd_rn(__fsub_rn(x2A, __fadd_rn(dot1, dot1)), w2v.y);
            float d2 = __fadd_rn(__fsub_rn(x2B, __fadd_rn(dot2, dot2)), w2v.x);
            float d3 = __fadd_rn(__fsub_rn(x2B, __fadd_rn(dot3, dot3)), w2v.y);
            bestA = umin64(bestA, ((ull)__float_as_uint(d0) << 32) | (unsigned)c0);
            bestA = umin64(bestA, ((ull)__float_as_uint(d1) << 32) | (unsigned)(c0 + 1));
            bestB = umin64(bestB, ((ull)__float_as_uint(d2) << 32) | (unsigned)c0);
            bestB = umin64(bestB, ((ull)__float_as_uint(d3) << 32) | (unsigned)(c0 + 1));
        }
        // Epilogue tile v
        {
            int c0 = (t + 1) * 8 + cix;
            float2 w2v = *(const float2*)(pw2 + 8);
            float dot0 = __fmaf_rn(vc0, RSCALE_INV, vh0);
            float dot1 = __fmaf_rn(vc1, RSCALE_INV, vh1);
            float dot2 = __fmaf_rn(vc2, RSCALE_INV, vh2);
            float dot3 = __fmaf_rn(vc3, RSCALE_INV, vh3);
            float d0 = __fadd_rn(__fsub_rn(x2A, __fadd_rn(dot0, dot0)), w2v.x);
            float d1 = __fadd_rn(__fsub_rn(x2A, __fadd_rn(dot1, dot1)), w2v.y);
            float d2 = __fadd_rn(__fsub_rn(x2B, __fadd_rn(dot2, dot2)), w2v.x);
            float d3 = __fadd_rn(__fsub_rn(x2B, __fadd_rn(dot3, dot3)), w2v.y);
            bestA = umin64(bestA, ((ull)__float_as_uint(d0) << 32) | (unsigned)c0);
            bestA = umin64(bestA, ((ull)__float_as_uint(d1) << 32) | (unsigned)(c0 + 1));
            bestB = umin64(bestB, ((ull)__float_as_uint(d2) << 32) | (unsigned)c0);
            bestB = umin64(bestB, ((ull)__float_as_uint(d3) << 32) | (unsigned)(c0 + 1));
        }
        pw2 += 16;
    }

    // Cross-lane argmin (lanes sharing a row group); ties -> smaller k
    bestA = umin64(bestA, __shfl_xor_sync(0xFFFFFFFFu, bestA, 1));
    bestA = umin64(bestA, __shfl_xor_sync(0xFFFFFFFFu, bestA, 2));
    bestB = umin64(bestB, __shfl_xor_sync(0xFFFFFFFFu, bestB, 1));
    bestB = umin64(bestB, __shfl_xor_sync(0xFFFFFFFFu, bestB, 2));

    const int biA = (int)(unsigned)(bestA & 0xFFFFFFFFull);
    const int biB = (int)(unsigned)(bestB & 0xFFFFFFFFull);
    const int rA  = rowbase + r0 + (lane >> 2);
    const int rB  = rA + 8;

    if ((lane & 3) == 0) {
        out[rA] = (float)biA;
        out[rB] = (float)biB;
    }

    // Fused gather + straight-through + loss; 4 lanes split a row into 4 chunks
    float s0 = 0.f, s1 = 0.f, s2 = 0.f, s3 = 0.f;
    const int j0 = (lane & 3) * 4;
    #pragma unroll
    for (int r = 0; r < 2; r++) {
        const int row = r ? rB : rA;
        const int bi  = r ? biB : biA;
        const float4* xg = (const float4*)(enc + (size_t)row * DIM);
        const float4* qg = (const float4*)(W + (size_t)bi * DIM);
        float4* o = (float4*)(out + NROWS + (size_t)row * DIM);
        #pragma unroll
        for (int s = 0; s < 4; s++) {
            int j = j0 + s;
            float4 x = xg[j];
            float4 q = __ldg(&qg[j]);
            float d0 = __fsub_rn(q.x, x.x);
            float d1 = __fsub_rn(q.y, x.y);
            float d2 = __fsub_rn(q.z, x.z);
            float d3 = __fsub_rn(q.w, x.w);
            float4 rr;
            rr.x = __fadd_rn(x.x, d0);   // straight-through: fl(x + fl(q - x))
            rr.y = __fadd_rn(x.y, d1);
            rr.z = __fadd_rn(x.z, d2);
            rr.w = __fadd_rn(x.w, d3);
            o[j] = rr;
            s0 = __fmaf_rn(d0, d0, s0);
            s1 = __fmaf_rn(d1, d1, s1);
            s2 = __fmaf_rn(d2, d2, s2);
            s3 = __fmaf_rn(d3, d3, s3);
        }
    }
    double lsum = (double)((s0 + s1) + (s2 + s3));

    // Loss reduction: warp -> CTA -> global ticket
    #pragma unroll
    for (int off = 16; off > 0; off >>= 1)
        lsum += __shfl_xor_sync(0xFFFFFFFFu, lsum, off);

    double* swarp = (double*)(sm + SM_RED);
    __shared__ bool s_last;
    if (lane == 0) swarp[wid] = lsum;
    __syncthreads();

    if (tid == 0) {
        double bsum = 0.0;
        #pragma unroll
        for (int w = 0; w < THREADS / 32; w++) bsum += swarp[w];
        g_partials[blockIdx.x] = bsum;
        __threadfence();
        unsigned old = atomicAdd(&g_ticket, 1u);
        s_last = (old == BLOCKS - 1);
    }
    __syncthreads();

    if (s_last) {
        double t = 0.0;
        for (int i = tid; i < BLOCKS; i += THREADS) t += g_partials[i];
        #pragma unroll
        for (int off = 16; off > 0; off >>= 1)
            t += __shfl_xor_sync(0xFFFFFFFFu, t, off);
        if (lane == 0) swarp[wid] = t;
        __syncthreads();
        if (tid == 0) {
            double tot = 0.0;
            #pragma unroll
            for (int w = 0; w < THREADS / 32; w++) tot += swarp[w];
            float m = (float)(tot / (double)((size_t)NROWS * DIM));
            // vq_loss = fl(fl(mean*0.25) + mean)
            out[(size_t)NROWS * (DIM + 1)] = __fadd_rn(__fmul_rn(m, 0.25f), m);
            g_ticket = 0;   // deterministic across graph replays
        }
    }
}

extern "C" void kernel_launch(void* const* d_in, const int* in_sizes, int n_in,
                              void* d_out, int out_size) {
    const float* enc = (const float*)d_in[0];   // [N, 64] fp32
    const float* W   = (const float*)d_in[1];   // [512, 64] fp32
    float* out = (float*)d_out;                 // [N | N*64 | 1] fp32

    cudaFuncSetAttribute(vq_main,
                         cudaFuncAttributeMaxDynamicSharedMemorySize, SMEM_BYTES);

    vq_prep<<<KCB / 128, 128>>>(W);
    vq_main<<<BLOCKS, THREADS, SMEM_BYTES>>>(enc, W, out);
}